// round 12
// baseline (speedup 1.0000x reference)
#include <cuda_runtime.h>
#include <cuda_bf16.h>
#include <cstdint>

// ---------------------------------------------------------------------------
// MTL2d_DeepSVDD: 3x (conv s2 + relu -> MHSA(relpos bias) + residual) -> pool -> linear
// B=32, heads=3, dims {16,32,64}, dh {5,10,21}, inner {15,30,63}, N {1024,256,64}
// 10 launches: conv1, attn1(qkv fused), outproj1, conv2, attn2(qkv fused),
//              outproj2, conv3, proj3, attn3, outproj_pool_cls
// ---------------------------------------------------------------------------

#define BATCH 32
#define HEADS 3

__device__ float g_z1[BATCH * 16 * 32 * 32];
__device__ float g_z2[BATCH * 32 * 16 * 16];
__device__ float g_z3[BATCH * 64 * 8 * 8];
__device__ float g_qkv[BATCH * 189 * 64];
__device__ float g_att[BATCH * 15 * 1024];

// ---------------- packed f32x2 helpers --------------------------------------
__device__ __forceinline__ unsigned long long pk2(float x, float y) {
    unsigned long long r;
    asm("mov.b64 %0, {%1, %2};" : "=l"(r) : "f"(x), "f"(y));
    return r;
}
__device__ __forceinline__ void upk2(unsigned long long v, float& x, float& y) {
    asm("mov.b64 {%0, %1}, %2;" : "=f"(x), "=f"(y) : "l"(v));
}
__device__ __forceinline__ unsigned long long fma2(unsigned long long a,
                                                   unsigned long long b,
                                                   unsigned long long c) {
    unsigned long long d;
    asm("fma.rn.f32x2 %0, %1, %2, %3;" : "=l"(d) : "l"(a), "l"(b), "l"(c));
    return d;
}
__device__ __forceinline__ unsigned long long add2(unsigned long long a,
                                                   unsigned long long b) {
    unsigned long long d;
    asm("add.rn.f32x2 %0, %1, %2;" : "=l"(d) : "l"(a), "l"(b));
    return d;
}
__device__ __forceinline__ float ex2f(float x) {
    float y;
    asm("ex2.approx.ftz.f32 %0, %1;" : "=f"(y) : "f"(x));
    return y;
}

// ---------------------------------------------------------------------------
// conv 3x3 stride-2 pad-1 + bias + relu (round-8 proven v2)
// ---------------------------------------------------------------------------
template<int CIN, int COUT, int HIN, int HOUT, int OXPT>
__global__ void __launch_bounds__(256)
conv_s2_relu_v2(const float* __restrict__ x,
                const float* __restrict__ w,
                const float* __restrict__ bias,
                float* __restrict__ y) {
    extern __shared__ float sw[];   // [(CIN*9)][COUT]
    int tid = threadIdx.x;
    for (int i = tid; i < COUT * CIN * 9; i += 256) {
        int co = i / (CIN * 9);
        int r  = i % (CIN * 9);
        sw[r * COUT + co] = w[i];
    }
    __syncthreads();

    constexpr int OXG = HOUT / OXPT;
    int idx = blockIdx.x * 256 + tid;
    int oxp = idx % OXG;
    int t   = idx / OXG;
    int oy  = t % HOUT; t /= HOUT;
    int cog = t % (COUT / 4);
    int b   = t / (COUT / 4);

    int c0  = cog * 4;
    int ox0 = oxp * OXPT;
    const float* xb = x + (size_t)b * CIN * HIN * HIN;

    unsigned long long a0p = pk2(bias[c0], bias[c0 + 1]);
    unsigned long long a0q = pk2(bias[c0 + 2], bias[c0 + 3]);
    unsigned long long a1p = a0p, a1q = a0q;

    constexpr int NX = (OXPT == 2) ? 5 : 3;
    int ixb = ox0 * 2 - 1;

    for (int ci = 0; ci < CIN; ci++) {
        #pragma unroll
        for (int ky = 0; ky < 3; ky++) {
            int iy = oy * 2 - 1 + ky;
            if ((unsigned)iy >= (unsigned)HIN) continue;
            const float* row = xb + (ci * HIN + iy) * HIN;
            float xv[NX];
            #pragma unroll
            for (int u = 0; u < NX; u++) {
                int ix = ixb + u;
                xv[u] = ((unsigned)ix < (unsigned)HIN) ? row[ix] : 0.0f;
            }
            const float* wp = &sw[(ci * 9 + ky * 3) * COUT + c0];
            #pragma unroll
            for (int kx = 0; kx < 3; kx++) {
                unsigned long long w01 = *(const unsigned long long*)(wp + kx * COUT);
                unsigned long long w23 = *(const unsigned long long*)(wp + kx * COUT + 2);
                unsigned long long x0 = pk2(xv[kx], xv[kx]);
                a0p = fma2(x0, w01, a0p);
                a0q = fma2(x0, w23, a0q);
                if (OXPT == 2) {
                    unsigned long long x1 = pk2(xv[kx + 2], xv[kx + 2]);
                    a1p = fma2(x1, w01, a1p);
                    a1q = fma2(x1, w23, a1q);
                }
            }
        }
    }

    float v0[4], v1[4];
    upk2(a0p, v0[0], v0[1]); upk2(a0q, v0[2], v0[3]);
    upk2(a1p, v1[0], v1[1]); upk2(a1q, v1[2], v1[3]);
    #pragma unroll
    for (int r = 0; r < 4; r++) {
        size_t o = (((size_t)b * COUT + c0 + r) * HOUT + oy) * HOUT + ox0;
        if (OXPT == 2) {
            float2 st2 = make_float2(fmaxf(v0[r], 0.0f), fmaxf(v1[r], 0.0f));
            *(float2*)(y + o) = st2;
        } else {
            y[o] = fmaxf(v0[r], 0.0f);
        }
    }
}

// ---------------------------------------------------------------------------
// 1x1 projection, float4-vectorized along n (stage 3 only)
// ---------------------------------------------------------------------------
template<int C, int O, int N>
__global__ void proj1x1(const float* __restrict__ z,
                        const float* __restrict__ w,
                        const float* __restrict__ bias,
                        float* __restrict__ y) {
    int idx = blockIdx.x * blockDim.x + threadIdx.x;
    constexpr int N4 = N / 4;
    constexpr int TOTAL4 = BATCH * O * N4;
    if (idx >= TOTAL4) return;
    int n4 = idx % N4;
    int t  = idx / N4;
    int o = t % O;
    int b = t / O;
    float bo = bias[o];
    float4 s = make_float4(bo, bo, bo, bo);
    const float4* zb = (const float4*)(z + (size_t)b * C * N);
    const float* wr = w + (size_t)o * C;
    #pragma unroll
    for (int c = 0; c < C; c++) {
        float wv = wr[c];
        float4 zv = zb[c * N4 + n4];
        s.x += wv * zv.x; s.y += wv * zv.y; s.z += wv * zv.z; s.w += wv * zv.w;
    }
    ((float4*)y)[idx] = s;
}

// ---------------------------------------------------------------------------
// flash attention with IN-KERNEL qkv projection (stages 1-2).
// block = (b, h, q-slice). Projection phase: each thread owns whole z
// columns in registers (z read once per column per block, coalesced),
// computes K/V rows for the head; q-slice projected into sq. One extra
// __syncthreads, then the round-8 proven no-max attention body.
// ---------------------------------------------------------------------------
template<int N, int C, int D, int HH, int QBLK, int TQ>
__global__ void __launch_bounds__(256, 2)
attn_qkv_flash(const float* __restrict__ z,
               const float* __restrict__ qw,
               const float* __restrict__ qb,
               const float* __restrict__ table,
               float* __restrict__ o_out) {
    constexpr int INNER = 3 * D;
    constexpr int QPB = N / QBLK;
    constexpr int NPASS = QPB / (8 * TQ);
    constexpr int TW = 2 * HH - 1;

    __shared__ float sk[D][N];
    __shared__ float sv[D][N];
    __shared__ float st[TW * TW];
    __shared__ float sq[D * QPB];

    int qsec = blockIdx.x % QBLK;
    int bh   = blockIdx.x / QBLK;
    int b = bh / HEADS, h = bh % HEADS;
    const float* zb = z + (size_t)b * C * N;

    const float scl = rsqrtf((float)D) * 1.4426950408889634f;
    int tid = threadIdx.x;
    int q0 = qsec * QPB;

    // ---- bias table ----
    for (int i = tid; i < TW * TW; i += 256)
        st[i] = table[i * HEADS + h] * scl;

    // ---- K/V projection: one column per thread iteration ----
    for (int p = tid; p < N; p += 256) {
        float zc[C];
        #pragma unroll
        for (int c = 0; c < C; c++) zc[c] = zb[c * N + p];
        #pragma unroll
        for (int dd = 0; dd < D; dd++) {
            int krow = INNER + dd * HEADS + h;
            int vrow = 2 * INNER + dd * HEADS + h;
            float ka = qb[krow];
            float va = qb[vrow];
            const float* wkr = qw + (size_t)krow * C;
            const float* wvr = qw + (size_t)vrow * C;
            #pragma unroll
            for (int c = 0; c < C; c++) {
                ka += wkr[c] * zc[c];
                va += wvr[c] * zc[c];
            }
            sk[dd][p] = ka;
            sv[dd][p] = va;
        }
    }

    // ---- Q projection for this block's slice (pre-scaled) ----
    for (int i = tid; i < D * QPB; i += 256) {
        int dd = i / QPB, p = i % QPB;
        int qrow = dd * HEADS + h;
        float a = qb[qrow];
        const float* wqr = qw + (size_t)qrow * C;
        #pragma unroll
        for (int c = 0; c < C; c++) a += wqr[c] * zb[c * N + q0 + p];
        sq[i] = a * scl;
    }
    __syncthreads();

    int warp = tid >> 5, lane = tid & 31;

    for (int pass = 0; pass < NPASS; pass++) {
        int qr0 = (pass * 8 + warp) * TQ;
        int qg0 = q0 + qr0;

        unsigned long long qd[TQ][D];
        int At[TQ];
        #pragma unroll
        for (int t = 0; t < TQ; t++) {
            int q = qg0 + t;
            #pragma unroll
            for (int dd = 0; dd < D; dd++) {
                float qv = sq[dd * QPB + qr0 + t];
                qd[t][dd] = pk2(qv, qv);
            }
            int yq = q / HH, xq = q % HH;
            At[t] = (yq + HH - 1) * TW + xq + HH - 1;
        }

        unsigned long long l2[TQ];
        unsigned long long acc[TQ][D];
        #pragma unroll
        for (int t = 0; t < TQ; t++) {
            l2[t] = 0ull;
            #pragma unroll
            for (int dd = 0; dd < D; dd++) acc[t][dd] = 0ull;
        }

        for (int c0 = 0; c0 < N; c0 += 64) {
            int j  = c0 + lane * 2;
            int yk = j / HH, xk = j % HH;     // j even, HH even -> pair shares row
            int off = yk * TW + xk;

            unsigned long long p2[TQ];
            unsigned long long k2[D];
            #pragma unroll
            for (int dd = 0; dd < D; dd++)
                k2[dd] = *(const unsigned long long*)&sk[dd][j];
            #pragma unroll
            for (int t = 0; t < TQ; t++) {
                int ri = At[t] - off;
                unsigned long long sc = pk2(st[ri], st[ri - 1]);
                #pragma unroll
                for (int dd = 0; dd < D; dd++)
                    sc = fma2(qd[t][dd], k2[dd], sc);
                float a, bb; upk2(sc, a, bb);
                p2[t] = pk2(ex2f(a), ex2f(bb));
                l2[t] = add2(l2[t], p2[t]);
            }
            unsigned long long v2[D];
            #pragma unroll
            for (int dd = 0; dd < D; dd++)
                v2[dd] = *(const unsigned long long*)&sv[dd][j];
            #pragma unroll
            for (int t = 0; t < TQ; t++) {
                #pragma unroll
                for (int dd = 0; dd < D; dd++)
                    acc[t][dd] = fma2(p2[t], v2[dd], acc[t][dd]);
            }
        }

        #pragma unroll
        for (int t = 0; t < TQ; t++) {
            int q = qg0 + t;
            float lx, ly; upk2(l2[t], lx, ly);
            float ls = lx + ly;
            #pragma unroll
            for (int off = 16; off; off >>= 1)
                ls += __shfl_xor_sync(0xffffffffu, ls, off);
            float inv = 1.0f / ls;
            #pragma unroll
            for (int dd = 0; dd < D; dd++) {
                float ax, ay; upk2(acc[t][dd], ax, ay);
                float a = ax + ay;
                #pragma unroll
                for (int off = 16; off; off >>= 1)
                    a += __shfl_xor_sync(0xffffffffu, a, off);
                if (lane == 0)
                    o_out[((size_t)b * INNER + dd * HEADS + h) * N + q] = a * inv;
            }
        }
    }
}

// ---------------------------------------------------------------------------
// flash attention from precomputed qkv (stage 3 only; round-8 proven)
// ---------------------------------------------------------------------------
template<int N, int D, int HH, int QBLK, int TQ>
__global__ void __launch_bounds__(256, 2)
attn_flash(const float* __restrict__ qkv,
           const float* __restrict__ table,
           float* __restrict__ o_out) {
    constexpr int INNER = 3 * D;
    constexpr int QPB = N / QBLK;
    constexpr int NPASS = QPB / (8 * TQ);
    constexpr int TW = 2 * HH - 1;

    __shared__ float sk[D][N];
    __shared__ float sv[D][N];
    __shared__ float st[TW * TW];

    int qsec = blockIdx.x % QBLK;
    int bh   = blockIdx.x / QBLK;
    int b = bh / HEADS, h = bh % HEADS;
    const float* base = qkv + (size_t)b * 3 * INNER * N;

    const float scl = rsqrtf((float)D) * 1.4426950408889634f;

    int tid = threadIdx.x;
    for (int i = tid; i < D * (N / 4); i += 256) {
        int dd = i / (N / 4);
        int j4 = i % (N / 4);
        const float4* kr = (const float4*)(base + (size_t)(INNER + dd * HEADS + h) * N);
        const float4* vr = (const float4*)(base + (size_t)(2 * INNER + dd * HEADS + h) * N);
        ((float4*)&sk[dd][0])[j4] = kr[j4];
        ((float4*)&sv[dd][0])[j4] = vr[j4];
    }
    for (int i = tid; i < TW * TW; i += 256)
        st[i] = table[i * HEADS + h] * scl;
    __syncthreads();

    int warp = tid >> 5, lane = tid & 31;

    for (int pass = 0; pass < NPASS; pass++) {
        int q0 = qsec * QPB + (pass * 8 + warp) * TQ;

        unsigned long long qd[TQ][D];
        int At[TQ];
        #pragma unroll
        for (int t = 0; t < TQ; t++) {
            int q = q0 + t;
            #pragma unroll
            for (int dd = 0; dd < D; dd++) {
                float qv = base[(dd * HEADS + h) * N + q] * scl;
                qd[t][dd] = pk2(qv, qv);
            }
            int yq = q / HH, xq = q % HH;
            At[t] = (yq + HH - 1) * TW + xq + HH - 1;
        }

        unsigned long long l2[TQ];
        unsigned long long acc[TQ][D];
        #pragma unroll
        for (int t = 0; t < TQ; t++) {
            l2[t] = 0ull;
            #pragma unroll
            for (int dd = 0; dd < D; dd++) acc[t][dd] = 0ull;
        }

        for (int c0 = 0; c0 < N; c0 += 64) {
            int j  = c0 + lane * 2;
            int yk = j / HH, xk = j % HH;
            int off = yk * TW + xk;

            int ri = At[0] - off;
            unsigned long long sc = pk2(st[ri], st[ri - 1]);
            #pragma unroll
            for (int dd = 0; dd < D; dd++)
                sc = fma2(qd[0][dd], *(const unsigned long long*)&sk[dd][j], sc);
            float a, bb; upk2(sc, a, bb);
            unsigned long long p2 = pk2(ex2f(a), ex2f(bb));
            l2[0] = add2(l2[0], p2);
            #pragma unroll
            for (int dd = 0; dd < D; dd++)
                acc[0][dd] = fma2(p2, *(const unsigned long long*)&sv[dd][j], acc[0][dd]);
        }

        #pragma unroll
        for (int t = 0; t < TQ; t++) {
            int q = q0 + t;
            float lx, ly; upk2(l2[t], lx, ly);
            float ls = lx + ly;
            #pragma unroll
            for (int off = 16; off; off >>= 1)
                ls += __shfl_xor_sync(0xffffffffu, ls, off);
            float inv = 1.0f / ls;
            #pragma unroll
            for (int dd = 0; dd < D; dd++) {
                float ax, ay; upk2(acc[t][dd], ax, ay);
                float a = ax + ay;
                #pragma unroll
                for (int off = 16; off; off >>= 1)
                    a += __shfl_xor_sync(0xffffffffu, a, off);
                if (lane == 0)
                    o_out[((size_t)b * INNER + dd * HEADS + h) * N + q] = a * inv;
            }
        }
    }
}

// ---------------------------------------------------------------------------
// out projection + residual (in-place on z), float4-vectorized along n
// ---------------------------------------------------------------------------
template<int INNER, int DIM, int N>
__global__ void outproj_res(const float* __restrict__ o,
                            const float* __restrict__ w,
                            const float* __restrict__ bias,
                            float* __restrict__ z) {
    int idx = blockIdx.x * blockDim.x + threadIdx.x;
    constexpr int N4 = N / 4;
    constexpr int TOTAL4 = BATCH * DIM * N4;
    if (idx >= TOTAL4) return;
    int n4 = idx % N4;
    int t  = idx / N4;
    int c = t % DIM;
    int b = t / DIM;
    float4 s = ((float4*)z)[idx];
    float bc = bias[c];
    s.x += bc; s.y += bc; s.z += bc; s.w += bc;
    const float4* ob = (const float4*)(o + (size_t)b * INNER * N);
    const float* wr = w + (size_t)c * INNER;
    #pragma unroll
    for (int i = 0; i < INNER; i++) {
        float wv = wr[i];
        float4 ov = ob[i * N4 + n4];
        s.x += wv * ov.x; s.y += wv * ov.y; s.z += wv * ov.z; s.w += wv * ov.w;
    }
    ((float4*)z)[idx] = s;
}

// ---------------------------------------------------------------------------
// stage-3 tail: pooling commuted through out-proj, then classifier.
// ---------------------------------------------------------------------------
__global__ void outproj_pool_cls(const float* __restrict__ o,
                                 const float* __restrict__ w,
                                 const float* __restrict__ ob,
                                 const float* __restrict__ z3,
                                 const float* __restrict__ cw,
                                 const float* __restrict__ cb,
                                 float* __restrict__ out) {
    int b = blockIdx.x;
    int tid = threadIdx.x;   // 128 threads
    __shared__ float obar[63];
    __shared__ float zbar[64];
    __shared__ float m[64];

    if (tid < 63) {
        const float* op = o + ((size_t)b * 63 + tid) * 64;
        float s = 0.0f;
        #pragma unroll
        for (int n = 0; n < 64; n++) s += op[n];
        obar[tid] = s * (1.0f / 64.0f);
    } else if (tid >= 64) {
        int c = tid - 64;
        const float* zp = z3 + ((size_t)b * 64 + c) * 64;
        float s = 0.0f;
        #pragma unroll
        for (int n = 0; n < 64; n++) s += zp[n];
        zbar[c] = s * (1.0f / 64.0f);
    }
    __syncthreads();

    if (tid < 64) {
        float s = ob[tid] + zbar[tid];
        const float* wr = w + tid * 63;
        #pragma unroll
        for (int i = 0; i < 63; i++) s += wr[i] * obar[i];
        m[tid] = s;
        out[b * 64 + tid] = s;
    }
    __syncthreads();

    if (tid < 10) {
        float t = cb[tid];
        #pragma unroll
        for (int k = 0; k < 64; k++) t += cw[tid * 64 + k] * m[k];
        out[BATCH * 64 + b * 10 + tid] = t;
    }
}

// ---------------------------------------------------------------------------

static inline int blocks(int total, int tpb) { return (total + tpb - 1) / tpb; }

extern "C" void kernel_launch(void* const* d_in, const int* in_sizes, int n_in,
                              void* d_out, int out_size) {
    const float* x       = (const float*)d_in[0];
    const float* conv1_w = (const float*)d_in[1];
    const float* conv1_b = (const float*)d_in[2];
    const float* qkv1_w  = (const float*)d_in[3];
    const float* qkv1_b  = (const float*)d_in[4];
    const float* out1_w  = (const float*)d_in[5];
    const float* out1_b  = (const float*)d_in[6];
    const float* rel1    = (const float*)d_in[7];
    const float* conv2_w = (const float*)d_in[8];
    const float* conv2_b = (const float*)d_in[9];
    const float* qkv2_w  = (const float*)d_in[10];
    const float* qkv2_b  = (const float*)d_in[11];
    const float* out2_w  = (const float*)d_in[12];
    const float* out2_b  = (const float*)d_in[13];
    const float* rel2    = (const float*)d_in[14];
    const float* conv3_w = (const float*)d_in[15];
    const float* conv3_b = (const float*)d_in[16];
    const float* qkv3_w  = (const float*)d_in[17];
    const float* qkv3_b  = (const float*)d_in[18];
    const float* out3_w  = (const float*)d_in[19];
    const float* out3_b  = (const float*)d_in[20];
    const float* rel3    = (const float*)d_in[21];
    const float* cls_w   = (const float*)d_in[22];
    const float* cls_b   = (const float*)d_in[23];
    float* out = (float*)d_out;

    float *z1, *z2, *z3, *qkv, *att;
    cudaGetSymbolAddress((void**)&z1,  g_z1);
    cudaGetSymbolAddress((void**)&z2,  g_z2);
    cudaGetSymbolAddress((void**)&z3,  g_z3);
    cudaGetSymbolAddress((void**)&qkv, g_qkv);
    cudaGetSymbolAddress((void**)&att, g_att);

    const int TPB = 256;

    constexpr int CS1 = 16 * 1 * 9 * 4;      // 576 B
    constexpr int CS2 = 32 * 16 * 9 * 4;     // 18432 B
    constexpr int CS3 = 64 * 32 * 9 * 4;     // 73728 B
    cudaFuncSetAttribute((const void*)conv_s2_relu_v2<32, 64, 16, 8, 1>,
                         cudaFuncAttributeMaxDynamicSharedMemorySize, CS3);

    // ---- stage 1: N=1024, C=16, d=5 ----
    conv_s2_relu_v2<1, 16, 64, 32, 2><<<BATCH*4*32*16/256, 256, CS1>>>(x, conv1_w, conv1_b, z1);
    attn_qkv_flash<1024, 16, 5, 32, 8, 4><<<BATCH*HEADS*8, 256>>>(z1, qkv1_w, qkv1_b, rel1, att);
    outproj_res<15, 16, 1024><<<blocks(BATCH*16*256, TPB), TPB>>>(att, out1_w, out1_b, z1);

    // ---- stage 2: N=256, C=32, d=10 ----
    conv_s2_relu_v2<16, 32, 32, 16, 2><<<BATCH*8*16*8/256, 256, CS2>>>(z1, conv2_w, conv2_b, z2);
    attn_qkv_flash<256, 32, 10, 16, 2, 2><<<BATCH*HEADS*2, 256>>>(z2, qkv2_w, qkv2_b, rel2, att);
    outproj_res<30, 32, 256><<<blocks(BATCH*32*64, TPB), TPB>>>(att, out2_w, out2_b, z2);

    // ---- stage 3: N=64, C=64, d=21 ----
    conv_s2_relu_v2<32, 64, 16, 8, 1><<<BATCH*16*8*8/256, 256, CS3>>>(z2, conv3_w, conv3_b, z3);
    proj1x1<64, 189, 64><<<blocks(BATCH*189*16, TPB), TPB>>>(z3, qkv3_w, qkv3_b, qkv);
    attn_flash<64, 21, 8, 1, 1><<<BATCH*HEADS, 256>>>(qkv, rel3, att);

    // ---- fused stage-3 out-proj + pool + classifier ----
    outproj_pool_cls<<<BATCH, 128>>>(att, out3_w, out3_b, z3, cls_w, cls_b, out);
}

// round 13
// speedup vs baseline: 1.0495x; 1.0495x over previous
#include <cuda_runtime.h>
#include <cuda_bf16.h>
#include <cstdint>

// ---------------------------------------------------------------------------
// MTL2d_DeepSVDD: 3x (conv s2 + relu -> MHSA(relpos bias) + residual) -> pool -> linear
// B=32, heads=3, dims {16,32,64}, dh {5,10,21}, inner {15,30,63}, N {1024,256,64}
// 12 launches (round-8 structure); convs rebuilt: transposed weights prepared
// in the conv1 node, conv2/conv3 are smem-free with 2x blocks.
// ---------------------------------------------------------------------------

#define BATCH 32
#define HEADS 3

__device__ float g_z1[BATCH * 16 * 32 * 32];
__device__ float g_z2[BATCH * 32 * 16 * 16];
__device__ float g_z3[BATCH * 64 * 8 * 8];
__device__ float g_qkv[BATCH * 45 * 1024];
__device__ float g_att[BATCH * 15 * 1024];
__device__ float g_w2t[16 * 9 * 32];    // conv2 weights, [ci*9+k][co]
__device__ float g_w3t[32 * 9 * 64];    // conv3 weights, [ci*9+k][co]

// ---------------- packed f32x2 helpers --------------------------------------
__device__ __forceinline__ unsigned long long pk2(float x, float y) {
    unsigned long long r;
    asm("mov.b64 %0, {%1, %2};" : "=l"(r) : "f"(x), "f"(y));
    return r;
}
__device__ __forceinline__ void upk2(unsigned long long v, float& x, float& y) {
    asm("mov.b64 {%0, %1}, %2;" : "=f"(x), "=f"(y) : "l"(v));
}
__device__ __forceinline__ unsigned long long fma2(unsigned long long a,
                                                   unsigned long long b,
                                                   unsigned long long c) {
    unsigned long long d;
    asm("fma.rn.f32x2 %0, %1, %2, %3;" : "=l"(d) : "l"(a), "l"(b), "l"(c));
    return d;
}
__device__ __forceinline__ unsigned long long add2(unsigned long long a,
                                                   unsigned long long b) {
    unsigned long long d;
    asm("add.rn.f32x2 %0, %1, %2;" : "=l"(d) : "l"(a), "l"(b));
    return d;
}
__device__ __forceinline__ float ex2f(float x) {
    float y;
    asm("ex2.approx.ftz.f32 %0, %1;" : "=f"(y) : "f"(x));
    return y;
}

// ---------------------------------------------------------------------------
// conv1 (CIN=1) + transpose tail for conv2/conv3 weights.
// v2-style: 4 channels x 2 pixels per thread, tiny smem repack (144 floats).
// ---------------------------------------------------------------------------
__global__ void __launch_bounds__(256)
conv1_plus(const float* __restrict__ x,
           const float* __restrict__ w,
           const float* __restrict__ bias,
           float* __restrict__ y,
           const float* __restrict__ w2,
           const float* __restrict__ w3,
           float* __restrict__ w2t,
           float* __restrict__ w3t) {
    constexpr int COUT = 16, HIN = 64, HOUT = 32;
    __shared__ float sw[9 * COUT];
    int tid = threadIdx.x;
    if (tid < 144) {
        int co = tid / 9, k = tid % 9;
        sw[k * COUT + co] = w[tid];
    }
    __syncthreads();

    int idx = blockIdx.x * 256 + tid;
    int oxp = idx % 16;
    int t   = idx / 16;
    int oy  = t % HOUT; t /= HOUT;
    int cog = t % 4;
    int b   = t / 4;

    int c0  = cog * 4;
    int ox0 = oxp * 2;
    const float* xb = x + (size_t)b * HIN * HIN;

    unsigned long long a0p = pk2(bias[c0], bias[c0 + 1]);
    unsigned long long a0q = pk2(bias[c0 + 2], bias[c0 + 3]);
    unsigned long long a1p = a0p, a1q = a0q;

    int ixb = ox0 * 2 - 1;
    #pragma unroll
    for (int ky = 0; ky < 3; ky++) {
        int iy = oy * 2 - 1 + ky;
        if ((unsigned)iy >= (unsigned)HIN) continue;
        const float* row = xb + iy * HIN;
        float xv[5];
        #pragma unroll
        for (int u = 0; u < 5; u++) {
            int ix = ixb + u;
            xv[u] = ((unsigned)ix < (unsigned)HIN) ? row[ix] : 0.0f;
        }
        const float* wp = &sw[(ky * 3) * COUT + c0];
        #pragma unroll
        for (int kx = 0; kx < 3; kx++) {
            unsigned long long w01 = *(const unsigned long long*)(wp + kx * COUT);
            unsigned long long w23 = *(const unsigned long long*)(wp + kx * COUT + 2);
            unsigned long long x0 = pk2(xv[kx], xv[kx]);
            unsigned long long x1 = pk2(xv[kx + 2], xv[kx + 2]);
            a0p = fma2(x0, w01, a0p);
            a0q = fma2(x0, w23, a0q);
            a1p = fma2(x1, w01, a1p);
            a1q = fma2(x1, w23, a1q);
        }
    }

    float v0[4], v1[4];
    upk2(a0p, v0[0], v0[1]); upk2(a0q, v0[2], v0[3]);
    upk2(a1p, v1[0], v1[1]); upk2(a1q, v1[2], v1[3]);
    #pragma unroll
    for (int r = 0; r < 4; r++) {
        size_t o = (((size_t)b * COUT + c0 + r) * HOUT + oy) * HOUT + ox0;
        *(float2*)(y + o) = make_float2(fmaxf(v0[r], 0.0f), fmaxf(v1[r], 0.0f));
    }

    // ---- tail: transpose conv2/conv3 weights to [k][co] ----
    // w2: [32][16*9] -> w2t[r*32+co]; w3: [64][32*9] -> w3t[r*64+co]
    constexpr int W2N = 32 * 144;   // 4608
    constexpr int W3N = 64 * 288;   // 18432
    for (int i = idx; i < W2N + W3N; i += gridDim.x * 256) {
        if (i < W2N) {
            int co = i / 144, r = i % 144;
            w2t[r * 32 + co] = w2[i];
        } else {
            int j = i - W2N;
            int co = j / 288, r = j % 288;
            w3t[r * 64 + co] = w3[j];
        }
    }
}

// ---------------------------------------------------------------------------
// conv 3x3 s2 p1 + bias + relu from pre-transposed weights [k][co]:
// no smem, no sync; thread = (b, CPG channels, oy, ox); even/odd-ci dual
// accumulators halve the fma dependency chain. Warp-uniform weight LDGs.
// ---------------------------------------------------------------------------
template<int CIN, int COUT, int HIN, int HOUT, int CPG>
__global__ void __launch_bounds__(256)
conv_gmem(const float* __restrict__ x,
          const float* __restrict__ wt,
          const float* __restrict__ bias,
          float* __restrict__ y) {
    constexpr int NP = CPG / 2;
    int idx = blockIdx.x * 256 + threadIdx.x;
    int ox = idx % HOUT;
    int t  = idx / HOUT;
    int oy = t % HOUT; t /= HOUT;
    int cog = t % (COUT / CPG);
    int b   = t / (COUT / CPG);

    int c0 = cog * CPG;
    const float* xb = x + (size_t)b * CIN * HIN * HIN;

    unsigned long long accA[NP], accB[NP];
    #pragma unroll
    for (int p = 0; p < NP; p++) {
        accA[p] = pk2(bias[c0 + 2 * p], bias[c0 + 2 * p + 1]);
        accB[p] = 0ull;
    }

    int ixb = ox * 2 - 1;
    for (int ci = 0; ci < CIN; ci += 2) {
        #pragma unroll
        for (int par = 0; par < 2; par++) {
            int cc = ci + par;
            const float* rowbase = xb + (size_t)cc * HIN * HIN;
            #pragma unroll
            for (int ky = 0; ky < 3; ky++) {
                int iy = oy * 2 - 1 + ky;
                if ((unsigned)iy >= (unsigned)HIN) continue;
                const float* row = rowbase + iy * HIN;
                float xv[3];
                #pragma unroll
                for (int u = 0; u < 3; u++) {
                    int ix = ixb + u;
                    xv[u] = ((unsigned)ix < (unsigned)HIN) ? row[ix] : 0.0f;
                }
                const float* wp = wt + (cc * 9 + ky * 3) * COUT + c0;
                #pragma unroll
                for (int kx = 0; kx < 3; kx++) {
                    unsigned long long x2 = pk2(xv[kx], xv[kx]);
                    #pragma unroll
                    for (int p = 0; p < NP; p++) {
                        unsigned long long wv =
                            *(const unsigned long long*)(wp + kx * COUT + 2 * p);
                        if (par == 0) accA[p] = fma2(x2, wv, accA[p]);
                        else          accB[p] = fma2(x2, wv, accB[p]);
                    }
                }
            }
        }
    }

    #pragma unroll
    for (int p = 0; p < NP; p++) {
        accA[p] = add2(accA[p], accB[p]);
        float va, vb; upk2(accA[p], va, vb);
        size_t o = (((size_t)b * COUT + c0 + 2 * p) * HOUT + oy) * HOUT + ox;
        y[o] = fmaxf(va, 0.0f);
        y[o + (size_t)HOUT * HOUT] = fmaxf(vb, 0.0f);
    }
}

// ---------------------------------------------------------------------------
// 1x1 projection, float4-vectorized along n
// ---------------------------------------------------------------------------
template<int C, int O, int N>
__global__ void proj1x1(const float* __restrict__ z,
                        const float* __restrict__ w,
                        const float* __restrict__ bias,
                        float* __restrict__ y) {
    int idx = blockIdx.x * blockDim.x + threadIdx.x;
    constexpr int N4 = N / 4;
    constexpr int TOTAL4 = BATCH * O * N4;
    if (idx >= TOTAL4) return;
    int n4 = idx % N4;
    int t  = idx / N4;
    int o = t % O;
    int b = t / O;
    float bo = bias[o];
    float4 s = make_float4(bo, bo, bo, bo);
    const float4* zb = (const float4*)(z + (size_t)b * C * N);
    const float* wr = w + (size_t)o * C;
    #pragma unroll
    for (int c = 0; c < C; c++) {
        float wv = wr[c];
        float4 zv = zb[c * N4 + n4];
        s.x += wv * zv.x; s.y += wv * zv.y; s.z += wv * zv.z; s.w += wv * zv.w;
    }
    ((float4*)y)[idx] = s;
}

// ---------------------------------------------------------------------------
// flash attention, NO-MAX single-pass softmax (scores provably tiny for this
// model; exp2 without max-subtraction is exact softmax here).
// block = (b, h, q-slice). K,V + de-headed pre-scaled bias table in SMEM.
// ---------------------------------------------------------------------------
template<int N, int D, int HH, int QBLK, int TQ>
__global__ void __launch_bounds__(256, 2)
attn_flash(const float* __restrict__ qkv,
           const float* __restrict__ table,
           float* __restrict__ o_out) {
    constexpr int INNER = 3 * D;
    constexpr int QPB = N / QBLK;
    constexpr int NPASS = QPB / (8 * TQ);
    constexpr int TW = 2 * HH - 1;

    __shared__ float sk[D][N];
    __shared__ float sv[D][N];
    __shared__ float st[TW * TW];

    int qsec = blockIdx.x % QBLK;
    int bh   = blockIdx.x / QBLK;
    int b = bh / HEADS, h = bh % HEADS;
    const float* base = qkv + (size_t)b * 3 * INNER * N;

    const float scl = rsqrtf((float)D) * 1.4426950408889634f;

    int tid = threadIdx.x;
    for (int i = tid; i < D * (N / 4); i += 256) {
        int dd = i / (N / 4);
        int j4 = i % (N / 4);
        const float4* kr = (const float4*)(base + (size_t)(INNER + dd * HEADS + h) * N);
        const float4* vr = (const float4*)(base + (size_t)(2 * INNER + dd * HEADS + h) * N);
        ((float4*)&sk[dd][0])[j4] = kr[j4];
        ((float4*)&sv[dd][0])[j4] = vr[j4];
    }
    for (int i = tid; i < TW * TW; i += 256)
        st[i] = table[i * HEADS + h] * scl;
    __syncthreads();

    int warp = tid >> 5, lane = tid & 31;

    for (int pass = 0; pass < NPASS; pass++) {
        int q0 = qsec * QPB + (pass * 8 + warp) * TQ;

        unsigned long long qd[TQ][D];
        int At[TQ];
        #pragma unroll
        for (int t = 0; t < TQ; t++) {
            int q = q0 + t;
            #pragma unroll
            for (int dd = 0; dd < D; dd++) {
                float qv = base[(dd * HEADS + h) * N + q] * scl;
                qd[t][dd] = pk2(qv, qv);
            }
            int yq = q / HH, xq = q % HH;
            At[t] = (yq + HH - 1) * TW + xq + HH - 1;
        }

        unsigned long long l2[TQ];
        unsigned long long acc[TQ][D];
        #pragma unroll
        for (int t = 0; t < TQ; t++) {
            l2[t] = 0ull;
            #pragma unroll
            for (int dd = 0; dd < D; dd++) acc[t][dd] = 0ull;
        }

        for (int c0 = 0; c0 < N; c0 += 64) {
            int j  = c0 + lane * 2;
            int yk = j / HH, xk = j % HH;     // j even, HH even -> pair shares row
            int off = yk * TW + xk;

            unsigned long long p2[TQ];
            if constexpr (TQ > 1) {
                unsigned long long k2[D];
                #pragma unroll
                for (int dd = 0; dd < D; dd++)
                    k2[dd] = *(const unsigned long long*)&sk[dd][j];
                #pragma unroll
                for (int t = 0; t < TQ; t++) {
                    int ri = At[t] - off;
                    unsigned long long sc = pk2(st[ri], st[ri - 1]);
                    #pragma unroll
                    for (int dd = 0; dd < D; dd++)
                        sc = fma2(qd[t][dd], k2[dd], sc);
                    float a, bb; upk2(sc, a, bb);
                    p2[t] = pk2(ex2f(a), ex2f(bb));
                    l2[t] = add2(l2[t], p2[t]);
                }
                unsigned long long v2[D];
                #pragma unroll
                for (int dd = 0; dd < D; dd++)
                    v2[dd] = *(const unsigned long long*)&sv[dd][j];
                #pragma unroll
                for (int t = 0; t < TQ; t++) {
                    #pragma unroll
                    for (int dd = 0; dd < D; dd++)
                        acc[t][dd] = fma2(p2[t], v2[dd], acc[t][dd]);
                }
            } else {
                int ri = At[0] - off;
                unsigned long long sc = pk2(st[ri], st[ri - 1]);
                #pragma unroll
                for (int dd = 0; dd < D; dd++)
                    sc = fma2(qd[0][dd], *(const unsigned long long*)&sk[dd][j], sc);
                float a, bb; upk2(sc, a, bb);
                p2[0] = pk2(ex2f(a), ex2f(bb));
                l2[0] = add2(l2[0], p2[0]);
                #pragma unroll
                for (int dd = 0; dd < D; dd++)
                    acc[0][dd] = fma2(p2[0], *(const unsigned long long*)&sv[dd][j], acc[0][dd]);
            }
        }

        #pragma unroll
        for (int t = 0; t < TQ; t++) {
            int q = q0 + t;
            float lx, ly; upk2(l2[t], lx, ly);
            float ls = lx + ly;
            #pragma unroll
            for (int off = 16; off; off >>= 1)
                ls += __shfl_xor_sync(0xffffffffu, ls, off);
            float inv = 1.0f / ls;
            #pragma unroll
            for (int dd = 0; dd < D; dd++) {
                float ax, ay; upk2(acc[t][dd], ax, ay);
                float a = ax + ay;
                #pragma unroll
                for (int off = 16; off; off >>= 1)
                    a += __shfl_xor_sync(0xffffffffu, a, off);
                if (lane == 0)
                    o_out[((size_t)b * INNER + dd * HEADS + h) * N + q] = a * inv;
            }
        }
    }
}

// ---------------------------------------------------------------------------
// out projection + residual (in-place on z), float4-vectorized along n
// ---------------------------------------------------------------------------
template<int INNER, int DIM, int N>
__global__ void outproj_res(const float* __restrict__ o,
                            const float* __restrict__ w,
                            const float* __restrict__ bias,
                            float* __restrict__ z) {
    int idx = blockIdx.x * blockDim.x + threadIdx.x;
    constexpr int N4 = N / 4;
    constexpr int TOTAL4 = BATCH * DIM * N4;
    if (idx >= TOTAL4) return;
    int n4 = idx % N4;
    int t  = idx / N4;
    int c = t % DIM;
    int b = t / DIM;
    float4 s = ((float4*)z)[idx];
    float bc = bias[c];
    s.x += bc; s.y += bc; s.z += bc; s.w += bc;
    const float4* ob = (const float4*)(o + (size_t)b * INNER * N);
    const float* wr = w + (size_t)c * INNER;
    #pragma unroll
    for (int i = 0; i < INNER; i++) {
        float wv = wr[i];
        float4 ov = ob[i * N4 + n4];
        s.x += wv * ov.x; s.y += wv * ov.y; s.z += wv * ov.z; s.w += wv * ov.w;
    }
    ((float4*)z)[idx] = s;
}

// ---------------------------------------------------------------------------
// stage-3 tail: pooling commuted through out-proj, then classifier.
// ---------------------------------------------------------------------------
__global__ void outproj_pool_cls(const float* __restrict__ o,
                                 const float* __restrict__ w,
                                 const float* __restrict__ ob,
                                 const float* __restrict__ z3,
                                 const float* __restrict__ cw,
                                 const float* __restrict__ cb,
                                 float* __restrict__ out) {
    int b = blockIdx.x;
    int tid = threadIdx.x;   // 128 threads
    __shared__ float obar[63];
    __shared__ float zbar[64];
    __shared__ float m[64];

    if (tid < 63) {
        const float* op = o + ((size_t)b * 63 + tid) * 64;
        float s = 0.0f;
        #pragma unroll
        for (int n = 0; n < 64; n++) s += op[n];
        obar[tid] = s * (1.0f / 64.0f);
    } else if (tid >= 64) {
        int c = tid - 64;
        const float* zp = z3 + ((size_t)b * 64 + c) * 64;
        float s = 0.0f;
        #pragma unroll
        for (int n = 0; n < 64; n++) s += zp[n];
        zbar[c] = s * (1.0f / 64.0f);
    }
    __syncthreads();

    if (tid < 64) {
        float s = ob[tid] + zbar[tid];
        const float* wr = w + tid * 63;
        #pragma unroll
        for (int i = 0; i < 63; i++) s += wr[i] * obar[i];
        m[tid] = s;
        out[b * 64 + tid] = s;
    }
    __syncthreads();

    if (tid < 10) {
        float t = cb[tid];
        #pragma unroll
        for (int k = 0; k < 64; k++) t += cw[tid * 64 + k] * m[k];
        out[BATCH * 64 + b * 10 + tid] = t;
    }
}

// ---------------------------------------------------------------------------

static inline int blocks(int total, int tpb) { return (total + tpb - 1) / tpb; }

extern "C" void kernel_launch(void* const* d_in, const int* in_sizes, int n_in,
                              void* d_out, int out_size) {
    const float* x       = (const float*)d_in[0];
    const float* conv1_w = (const float*)d_in[1];
    const float* conv1_b = (const float*)d_in[2];
    const float* qkv1_w  = (const float*)d_in[3];
    const float* qkv1_b  = (const float*)d_in[4];
    const float* out1_w  = (const float*)d_in[5];
    const float* out1_b  = (const float*)d_in[6];
    const float* rel1    = (const float*)d_in[7];
    const float* conv2_w = (const float*)d_in[8];
    const float* conv2_b = (const float*)d_in[9];
    const float* qkv2_w  = (const float*)d_in[10];
    const float* qkv2_b  = (const float*)d_in[11];
    const float* out2_w  = (const float*)d_in[12];
    const float* out2_b  = (const float*)d_in[13];
    const float* rel2    = (const float*)d_in[14];
    const float* conv3_w = (const float*)d_in[15];
    const float* conv3_b = (const float*)d_in[16];
    const float* qkv3_w  = (const float*)d_in[17];
    const float* qkv3_b  = (const float*)d_in[18];
    const float* out3_w  = (const float*)d_in[19];
    const float* out3_b  = (const float*)d_in[20];
    const float* rel3    = (const float*)d_in[21];
    const float* cls_w   = (const float*)d_in[22];
    const float* cls_b   = (const float*)d_in[23];
    float* out = (float*)d_out;

    float *z1, *z2, *z3, *qkv, *att, *w2t, *w3t;
    cudaGetSymbolAddress((void**)&z1,  g_z1);
    cudaGetSymbolAddress((void**)&z2,  g_z2);
    cudaGetSymbolAddress((void**)&z3,  g_z3);
    cudaGetSymbolAddress((void**)&qkv, g_qkv);
    cudaGetSymbolAddress((void**)&att, g_att);
    cudaGetSymbolAddress((void**)&w2t, g_w2t);
    cudaGetSymbolAddress((void**)&w3t, g_w3t);

    const int TPB = 256;

    // ---- stage 1: N=1024, C=16, d=5 (+ weight transpose tail) ----
    conv1_plus<<<256, 256>>>(x, conv1_w, conv1_b, z1, conv2_w, conv3_w, w2t, w3t);
    proj1x1<16, 45, 1024><<<blocks(BATCH*45*256, TPB), TPB>>>(z1, qkv1_w, qkv1_b, qkv);
    attn_flash<1024, 5, 32, 8, 4><<<BATCH*HEADS*8, 256>>>(qkv, rel1, att);
    outproj_res<15, 16, 1024><<<blocks(BATCH*16*256, TPB), TPB>>>(att, out1_w, out1_b, z1);

    // ---- stage 2: N=256, C=32, d=10 ----
    conv_gmem<16, 32, 32, 16, 4><<<256, 256>>>(z1, w2t, conv2_b, z2);
    proj1x1<32, 90, 256><<<blocks(BATCH*90*64, TPB), TPB>>>(z2, qkv2_w, qkv2_b, qkv);
    attn_flash<256, 10, 16, 2, 2><<<BATCH*HEADS*2, 256>>>(qkv, rel2, att);
    outproj_res<30, 32, 256><<<blocks(BATCH*32*64, TPB), TPB>>>(att, out2_w, out2_b, z2);

    // ---- stage 3: N=64, C=64, d=21 ----
    conv_gmem<32, 64, 16, 8, 2><<<256, 256>>>(z2, w3t, conv3_b, z3);
    proj1x1<64, 189, 64><<<blocks(BATCH*189*16, TPB), TPB>>>(z3, qkv3_w, qkv3_b, qkv);
    attn_flash<64, 21, 8, 1, 1><<<BATCH*HEADS, 256>>>(qkv, rel3, att);

    // ---- fused stage-3 out-proj + pool + classifier ----
    outproj_pool_cls<<<BATCH, 128>>>(att, out3_w, out3_b, z3, cls_w, cls_b, out);
}

// round 14
// speedup vs baseline: 1.0878x; 1.0365x over previous
#include <cuda_runtime.h>
#include <cuda_bf16.h>
#include <cstdint>

// ---------------------------------------------------------------------------
// MTL2d_DeepSVDD as ONE persistent megakernel (grid=148x256, software grid
// barriers). Phase bodies are the proven round-8 kernels, grid-strided.
// ---------------------------------------------------------------------------

#define BATCH 32
#define HEADS 3
#define NBLK 148

__device__ float g_z1[BATCH * 16 * 32 * 32];
__device__ float g_z2[BATCH * 32 * 16 * 16];
__device__ float g_z3[BATCH * 64 * 8 * 8];
__device__ float g_qkv1[BATCH * 45 * 1024];
__device__ float g_att1[BATCH * 15 * 1024];
__device__ float g_qkv2[BATCH * 90 * 256];
__device__ float g_att2[BATCH * 30 * 256];
__device__ float g_qkv3[BATCH * 189 * 64];
__device__ float g_att3[BATCH * 63 * 64];

__device__ int          g_bar_count = 0;
__device__ unsigned int g_bar_gen   = 0;

// ---------------- packed f32x2 helpers --------------------------------------
__device__ __forceinline__ unsigned long long pk2(float x, float y) {
    unsigned long long r;
    asm("mov.b64 %0, {%1, %2};" : "=l"(r) : "f"(x), "f"(y));
    return r;
}
__device__ __forceinline__ void upk2(unsigned long long v, float& x, float& y) {
    asm("mov.b64 {%0, %1}, %2;" : "=f"(x), "=f"(y) : "l"(v));
}
__device__ __forceinline__ unsigned long long fma2(unsigned long long a,
                                                   unsigned long long b,
                                                   unsigned long long c) {
    unsigned long long d;
    asm("fma.rn.f32x2 %0, %1, %2, %3;" : "=l"(d) : "l"(a), "l"(b), "l"(c));
    return d;
}
__device__ __forceinline__ unsigned long long add2(unsigned long long a,
                                                   unsigned long long b) {
    unsigned long long d;
    asm("add.rn.f32x2 %0, %1, %2;" : "=l"(d) : "l"(a), "l"(b));
    return d;
}
__device__ __forceinline__ float ex2f(float x) {
    float y;
    asm("ex2.approx.ftz.f32 %0, %1;" : "=f"(y) : "f"(x));
    return y;
}

// ---------------- software grid barrier (graph-replay safe) -----------------
__device__ __forceinline__ void grid_barrier() {
    __threadfence();
    __syncthreads();
    if (threadIdx.x == 0) {
        unsigned int gen = *(volatile unsigned int*)&g_bar_gen;
        if (atomicAdd(&g_bar_count, 1) == (int)gridDim.x - 1) {
            g_bar_count = 0;
            __threadfence();
            atomicAdd(&g_bar_gen, 1);
        } else {
            while (*(volatile unsigned int*)&g_bar_gen == gen) { __nanosleep(64); }
        }
    }
    __syncthreads();
}

// ---------------- conv phase (round-8 v2 body, grid-stride) -----------------
template<int CIN, int COUT, int HIN, int HOUT, int OXPT, bool LDCG>
__device__ void conv_phase(const float* __restrict__ x,
                           const float* __restrict__ w,
                           const float* __restrict__ bias,
                           float* __restrict__ y,
                           float* sw) {
    int tid = threadIdx.x;
    for (int i = tid; i < COUT * CIN * 9; i += 256) {
        int co = i / (CIN * 9);
        int r  = i % (CIN * 9);
        sw[r * COUT + co] = w[i];
    }
    __syncthreads();

    constexpr int OXG = HOUT / OXPT;
    constexpr int TOTAL = BATCH * (COUT / 4) * HOUT * OXG;
    constexpr int NX = (OXPT == 2) ? 5 : 3;

    for (int idx = blockIdx.x * 256 + tid; idx < TOTAL; idx += gridDim.x * 256) {
        int oxp = idx % OXG;
        int t   = idx / OXG;
        int oy  = t % HOUT; t /= HOUT;
        int cog = t % (COUT / 4);
        int b   = t / (COUT / 4);
        int c0  = cog * 4;
        int ox0 = oxp * OXPT;
        const float* xb = x + (size_t)b * CIN * HIN * HIN;

        unsigned long long a0p = pk2(bias[c0], bias[c0 + 1]);
        unsigned long long a0q = pk2(bias[c0 + 2], bias[c0 + 3]);
        unsigned long long a1p = a0p, a1q = a0q;
        int ixb = ox0 * 2 - 1;

        for (int ci = 0; ci < CIN; ci++) {
            #pragma unroll
            for (int ky = 0; ky < 3; ky++) {
                int iy = oy * 2 - 1 + ky;
                if ((unsigned)iy >= (unsigned)HIN) continue;
                const float* row = xb + (ci * HIN + iy) * HIN;
                float xv[NX];
                #pragma unroll
                for (int u = 0; u < NX; u++) {
                    int ix = ixb + u;
                    xv[u] = ((unsigned)ix < (unsigned)HIN)
                            ? (LDCG ? __ldcg(row + ix) : row[ix]) : 0.0f;
                }
                const float* wp = &sw[(ci * 9 + ky * 3) * COUT + c0];
                #pragma unroll
                for (int kx = 0; kx < 3; kx++) {
                    unsigned long long w01 = *(const unsigned long long*)(wp + kx * COUT);
                    unsigned long long w23 = *(const unsigned long long*)(wp + kx * COUT + 2);
                    unsigned long long x0 = pk2(xv[kx], xv[kx]);
                    a0p = fma2(x0, w01, a0p);
                    a0q = fma2(x0, w23, a0q);
                    if (OXPT == 2) {
                        unsigned long long x1 = pk2(xv[kx + 2], xv[kx + 2]);
                        a1p = fma2(x1, w01, a1p);
                        a1q = fma2(x1, w23, a1q);
                    }
                }
            }
        }

        float v0[4], v1[4];
        upk2(a0p, v0[0], v0[1]); upk2(a0q, v0[2], v0[3]);
        upk2(a1p, v1[0], v1[1]); upk2(a1q, v1[2], v1[3]);
        #pragma unroll
        for (int r = 0; r < 4; r++) {
            size_t o = (((size_t)b * COUT + c0 + r) * HOUT + oy) * HOUT + ox0;
            if (OXPT == 2)
                *(float2*)(y + o) = make_float2(fmaxf(v0[r], 0.0f), fmaxf(v1[r], 0.0f));
            else
                y[o] = fmaxf(v0[r], 0.0f);
        }
    }
}

// ---------------- 1x1 projection phase --------------------------------------
template<int C, int O, int N>
__device__ void proj_phase(const float* __restrict__ z,
                           const float* __restrict__ w,
                           const float* __restrict__ bias,
                           float* __restrict__ y) {
    constexpr int N4 = N / 4;
    constexpr int TOTAL4 = BATCH * O * N4;
    for (int idx = blockIdx.x * 256 + threadIdx.x; idx < TOTAL4; idx += gridDim.x * 256) {
        int n4 = idx % N4;
        int t  = idx / N4;
        int o = t % O;
        int b = t / O;
        float bo = bias[o];
        float4 s = make_float4(bo, bo, bo, bo);
        const float4* zb = (const float4*)(z + (size_t)b * C * N);
        const float* wr = w + (size_t)o * C;
        #pragma unroll
        for (int c = 0; c < C; c++) {
            float wv = wr[c];
            float4 zv = zb[c * N4 + n4];
            s.x += wv * zv.x; s.y += wv * zv.y; s.z += wv * zv.z; s.w += wv * zv.w;
        }
        ((float4*)y)[idx] = s;
    }
}

// ---------------- attention phase (round-8 no-max body, vb loop) ------------
template<int N, int D, int HH, int QBLK, int TQ>
__device__ void attn_phase(const float* __restrict__ qkv,
                           const float* __restrict__ table,
                           float* __restrict__ o_out,
                           float* smem) {
    constexpr int INNER = 3 * D;
    constexpr int QPB = N / QBLK;
    constexpr int NPASS = QPB / (8 * TQ);
    constexpr int TW = 2 * HH - 1;
    constexpr int NVB = BATCH * HEADS * QBLK;

    float* sk = smem;            // D*N
    float* sv = sk + D * N;      // D*N
    float* st = sv + D * N;      // TW*TW

    int tid = threadIdx.x;
    int warp = tid >> 5, lane = tid & 31;
    const float scl = rsqrtf((float)D) * 1.4426950408889634f;

    for (int vb = blockIdx.x; vb < NVB; vb += gridDim.x) {
        __syncthreads();
        int qsec = vb % QBLK;
        int bh   = vb / QBLK;
        int b = bh / HEADS, h = bh % HEADS;
        const float* base = qkv + (size_t)b * 3 * INNER * N;

        for (int i = tid; i < D * (N / 4); i += 256) {
            int dd = i / (N / 4);
            int j4 = i % (N / 4);
            ((float4*)&sk[dd * N])[j4] =
                ((const float4*)(base + (size_t)(INNER + dd * HEADS + h) * N))[j4];
            ((float4*)&sv[dd * N])[j4] =
                ((const float4*)(base + (size_t)(2 * INNER + dd * HEADS + h) * N))[j4];
        }
        for (int i = tid; i < TW * TW; i += 256)
            st[i] = table[i * HEADS + h] * scl;
        __syncthreads();

        for (int pass = 0; pass < NPASS; pass++) {
            int q0 = qsec * QPB + (pass * 8 + warp) * TQ;

            unsigned long long qd[TQ][D];
            int At[TQ];
            #pragma unroll
            for (int t = 0; t < TQ; t++) {
                int q = q0 + t;
                #pragma unroll
                for (int dd = 0; dd < D; dd++) {
                    float qv = base[(dd * HEADS + h) * N + q] * scl;
                    qd[t][dd] = pk2(qv, qv);
                }
                int yq = q / HH, xq = q % HH;
                At[t] = (yq + HH - 1) * TW + xq + HH - 1;
            }

            unsigned long long l2[TQ];
            unsigned long long acc[TQ][D];
            #pragma unroll
            for (int t = 0; t < TQ; t++) {
                l2[t] = 0ull;
                #pragma unroll
                for (int dd = 0; dd < D; dd++) acc[t][dd] = 0ull;
            }

            for (int c0 = 0; c0 < N; c0 += 64) {
                int j  = c0 + lane * 2;
                int yk = j / HH, xk = j % HH;   // j even, HH even -> pair shares row
                int off = yk * TW + xk;

                unsigned long long p2[TQ];
                if constexpr (TQ > 1) {
                    unsigned long long k2[D];
                    #pragma unroll
                    for (int dd = 0; dd < D; dd++)
                        k2[dd] = *(const unsigned long long*)&sk[dd * N + j];
                    #pragma unroll
                    for (int t = 0; t < TQ; t++) {
                        int ri = At[t] - off;
                        unsigned long long sc = pk2(st[ri], st[ri - 1]);
                        #pragma unroll
                        for (int dd = 0; dd < D; dd++)
                            sc = fma2(qd[t][dd], k2[dd], sc);
                        float a, bb; upk2(sc, a, bb);
                        p2[t] = pk2(ex2f(a), ex2f(bb));
                        l2[t] = add2(l2[t], p2[t]);
                    }
                    unsigned long long v2[D];
                    #pragma unroll
                    for (int dd = 0; dd < D; dd++)
                        v2[dd] = *(const unsigned long long*)&sv[dd * N + j];
                    #pragma unroll
                    for (int t = 0; t < TQ; t++) {
                        #pragma unroll
                        for (int dd = 0; dd < D; dd++)
                            acc[t][dd] = fma2(p2[t], v2[dd], acc[t][dd]);
                    }
                } else {
                    int ri = At[0] - off;
                    unsigned long long sc = pk2(st[ri], st[ri - 1]);
                    #pragma unroll
                    for (int dd = 0; dd < D; dd++)
                        sc = fma2(qd[0][dd], *(const unsigned long long*)&sk[dd * N + j], sc);
                    float a, bb; upk2(sc, a, bb);
                    p2[0] = pk2(ex2f(a), ex2f(bb));
                    l2[0] = add2(l2[0], p2[0]);
                    #pragma unroll
                    for (int dd = 0; dd < D; dd++)
                        acc[0][dd] = fma2(p2[0], *(const unsigned long long*)&sv[dd * N + j], acc[0][dd]);
                }
            }

            #pragma unroll
            for (int t = 0; t < TQ; t++) {
                int q = q0 + t;
                float lx, ly; upk2(l2[t], lx, ly);
                float ls = lx + ly;
                #pragma unroll
                for (int off2 = 16; off2; off2 >>= 1)
                    ls += __shfl_xor_sync(0xffffffffu, ls, off2);
                float inv = 1.0f / ls;
                #pragma unroll
                for (int dd = 0; dd < D; dd++) {
                    float ax, ay; upk2(acc[t][dd], ax, ay);
                    float a = ax + ay;
                    #pragma unroll
                    for (int off2 = 16; off2; off2 >>= 1)
                        a += __shfl_xor_sync(0xffffffffu, a, off2);
                    if (lane == 0)
                        o_out[((size_t)b * INNER + dd * HEADS + h) * N + q] = a * inv;
                }
            }
        }
    }
}

// ---------------- out-proj + residual phase ----------------------------------
template<int INNER, int DIM, int N>
__device__ void outproj_phase(const float* __restrict__ o,
                              const float* __restrict__ w,
                              const float* __restrict__ bias,
                              float* __restrict__ z) {
    constexpr int N4 = N / 4;
    constexpr int TOTAL4 = BATCH * DIM * N4;
    for (int idx = blockIdx.x * 256 + threadIdx.x; idx < TOTAL4; idx += gridDim.x * 256) {
        int n4 = idx % N4;
        int t  = idx / N4;
        int c = t % DIM;
        int b = t / DIM;
        float4 s = ((float4*)z)[idx];
        float bc = bias[c];
        s.x += bc; s.y += bc; s.z += bc; s.w += bc;
        const float4* ob = (const float4*)(o + (size_t)b * INNER * N);
        const float* wr = w + (size_t)c * INNER;
        #pragma unroll
        for (int i = 0; i < INNER; i++) {
            float wv = wr[i];
            float4 ov = ob[i * N4 + n4];
            s.x += wv * ov.x; s.y += wv * ov.y; s.z += wv * ov.z; s.w += wv * ov.w;
        }
        ((float4*)z)[idx] = s;
    }
}

// ---------------- stage-3 tail phase -----------------------------------------
__device__ void tail_phase(const float* __restrict__ o,
                           const float* __restrict__ w,
                           const float* __restrict__ ob,
                           const float* __restrict__ z3,
                           const float* __restrict__ cw,
                           const float* __restrict__ cb,
                           float* __restrict__ out,
                           float* smem) {
    float* obar = smem;
    float* zbar = smem + 64;
    float* m    = smem + 128;
    int tid = threadIdx.x;

    for (int b = blockIdx.x; b < BATCH; b += gridDim.x) {
        __syncthreads();
        if (tid < 63) {
            const float* op = o + ((size_t)b * 63 + tid) * 64;
            float s = 0.0f;
            #pragma unroll
            for (int n = 0; n < 64; n++) s += op[n];
            obar[tid] = s * (1.0f / 64.0f);
        } else if (tid >= 64 && tid < 128) {
            int c = tid - 64;
            const float* zp = z3 + ((size_t)b * 64 + c) * 64;
            float s = 0.0f;
            #pragma unroll
            for (int n = 0; n < 64; n++) s += zp[n];
            zbar[c] = s * (1.0f / 64.0f);
        }
        __syncthreads();
        if (tid < 64) {
            float s = ob[tid] + zbar[tid];
            const float* wr = w + tid * 63;
            #pragma unroll
            for (int i = 0; i < 63; i++) s += wr[i] * obar[i];
            m[tid] = s;
            out[b * 64 + tid] = s;
        }
        __syncthreads();
        if (tid < 10) {
            float t = cb[tid];
            #pragma unroll
            for (int k = 0; k < 64; k++) t += cw[tid * 64 + k] * m[k];
            out[BATCH * 64 + b * 10 + tid] = t;
        }
    }
}

// ---------------- the megakernel ---------------------------------------------
__global__ void __launch_bounds__(256)
megakernel(const float* __restrict__ x,
           const float* __restrict__ c1w, const float* __restrict__ c1b,
           const float* __restrict__ q1w, const float* __restrict__ q1b,
           const float* __restrict__ o1w, const float* __restrict__ o1b,
           const float* __restrict__ r1,
           const float* __restrict__ c2w, const float* __restrict__ c2b,
           const float* __restrict__ q2w, const float* __restrict__ q2b,
           const float* __restrict__ o2w, const float* __restrict__ o2b,
           const float* __restrict__ r2,
           const float* __restrict__ c3w, const float* __restrict__ c3b,
           const float* __restrict__ q3w, const float* __restrict__ q3b,
           const float* __restrict__ o3w, const float* __restrict__ o3b,
           const float* __restrict__ r3,
           const float* __restrict__ clw, const float* __restrict__ clb,
           float* __restrict__ out) {
    extern __shared__ float smem[];

    // ---- stage 1 ----
    conv_phase<1, 16, 64, 32, 2, false>(x, c1w, c1b, g_z1, smem);
    grid_barrier();
    proj_phase<16, 45, 1024>(g_z1, q1w, q1b, g_qkv1);
    grid_barrier();
    attn_phase<1024, 5, 32, 8, 4>(g_qkv1, r1, g_att1, smem);
    grid_barrier();
    outproj_phase<15, 16, 1024>(g_att1, o1w, o1b, g_z1);
    grid_barrier();

    // ---- stage 2 ----
    conv_phase<16, 32, 32, 16, 2, true>(g_z1, c2w, c2b, g_z2, smem);
    grid_barrier();
    proj_phase<32, 90, 256>(g_z2, q2w, q2b, g_qkv2);
    grid_barrier();
    attn_phase<256, 10, 16, 2, 2>(g_qkv2, r2, g_att2, smem);
    grid_barrier();
    outproj_phase<30, 32, 256>(g_att2, o2w, o2b, g_z2);
    grid_barrier();

    // ---- stage 3 ----
    conv_phase<32, 64, 16, 8, 1, true>(g_z2, c3w, c3b, g_z3, smem);
    grid_barrier();
    proj_phase<64, 189, 64>(g_z3, q3w, q3b, g_qkv3);
    grid_barrier();
    attn_phase<64, 21, 8, 1, 1>(g_qkv3, r3, g_att3, smem);
    grid_barrier();

    // ---- tail: out-proj (pool-commuted) + residual mean + classifier ----
    tail_phase(g_att3, o3w, o3b, g_z3, clw, clb, out, smem);
}

// ---------------------------------------------------------------------------

extern "C" void kernel_launch(void* const* d_in, const int* in_sizes, int n_in,
                              void* d_out, int out_size) {
    const float* x       = (const float*)d_in[0];
    const float* conv1_w = (const float*)d_in[1];
    const float* conv1_b = (const float*)d_in[2];
    const float* qkv1_w  = (const float*)d_in[3];
    const float* qkv1_b  = (const float*)d_in[4];
    const float* out1_w  = (const float*)d_in[5];
    const float* out1_b  = (const float*)d_in[6];
    const float* rel1    = (const float*)d_in[7];
    const float* conv2_w = (const float*)d_in[8];
    const float* conv2_b = (const float*)d_in[9];
    const float* qkv2_w  = (const float*)d_in[10];
    const float* qkv2_b  = (const float*)d_in[11];
    const float* out2_w  = (const float*)d_in[12];
    const float* out2_b  = (const float*)d_in[13];
    const float* rel2    = (const float*)d_in[14];
    const float* conv3_w = (const float*)d_in[15];
    const float* conv3_b = (const float*)d_in[16];
    const float* qkv3_w  = (const float*)d_in[17];
    const float* qkv3_b  = (const float*)d_in[18];
    const float* out3_w  = (const float*)d_in[19];
    const float* out3_b  = (const float*)d_in[20];
    const float* rel3    = (const float*)d_in[21];
    const float* cls_w   = (const float*)d_in[22];
    const float* cls_b   = (const float*)d_in[23];
    float* out = (float*)d_out;

    // dyn smem: max(conv3 weight repack 32*9*64 floats = 73728 B,
    //               attn1 2*5*1024+225 floats = 41860 B)
    constexpr int SMEM = 32 * 9 * 64 * 4;
    static bool attr_set = false;
    if (!attr_set) {
        cudaFuncSetAttribute((const void*)megakernel,
                             cudaFuncAttributeMaxDynamicSharedMemorySize, SMEM);
        attr_set = true;
    }

    megakernel<<<NBLK, 256, SMEM>>>(
        x, conv1_w, conv1_b, qkv1_w, qkv1_b, out1_w, out1_b, rel1,
        conv2_w, conv2_b, qkv2_w, qkv2_b, out2_w, out2_b, rel2,
        conv3_w, conv3_b, qkv3_w, qkv3_b, out3_w, out3_b, rel3,
        cls_w, cls_b, out);
}